// round 15
// baseline (speedup 1.0000x reference)
#include <cuda_runtime.h>
#include <cstdint>
#include <cstddef>

#define NFEAT 17
#define HDIM 8
#define BSZ 256
#define TSTEPS 512
#define XDIM 59
#define CHK 32
#define NCHK (TSTEPS/CHK)
#define BPC 2
#define NTHREADS 288
#define ROWPAD (CHK*XDIM + 16)   // pad so xp[d] overreads stay in-array

typedef unsigned long long u64;

// Chain-to-slot mapping. slot = warp*4 + group. Heavy warps d-homogeneous:
// w1={f3,f3,f2,f2} mdw13 (SMSP1), w2={f4,f4,f1,f1} mdw12 (SMSP2).
__device__ __constant__ int8_t c_slot_f[36] = {
   6, 6, 7, 7,   3, 3, 2, 2,   4, 4, 1, 1,   0, 0, 5, 5,
   8, 8, 9, 9,  10,10,11,11,  12,12,13,13,  14,14,15,15,  16,16,16,16};
__device__ __constant__ int8_t c_slot_b[36] = {
   0, 1, 0, 1,   0, 1, 0, 1,   0, 1, 0, 1,   0, 1, 0, 1,
   0, 1, 0, 1,   0, 1, 0, 1,   0, 1, 0, 1,   0, 1, 0, 1,   0, 1, 0, 1};
__device__ __constant__ int8_t c_slot_wr[36] = {
   1, 1, 1, 1,   1, 1, 1, 1,   1, 1, 1, 1,   1, 1, 1, 1,
   1, 1, 1, 1,   1, 1, 1, 1,   1, 1, 1, 1,   1, 1, 1, 1,   1, 1, 0, 0};
__device__ __constant__ int8_t c_warp_mdw[9] = {1,13,12,2,1,1,1,1,1};
__device__ __constant__ int8_t c_start[17] =
  {0,2,10,22,35,47,48,49,50,51,52,53,54,55,56,57,58};

template<int N> struct IC { static constexpr int value = N; };

__device__ __forceinline__ void cp16(uint32_t s, const float* g){
  asm volatile("cp.async.ca.shared.global [%0], [%1], 16;" :: "r"(s), "l"(g) : "memory");
}
__device__ __forceinline__ float tanh_ap(float x){
  float y; asm("tanh.approx.f32 %0, %1;" : "=f"(y) : "f"(x)); return y;
}
__device__ __forceinline__ u64 pk(float lo, float hi){
  u64 r; asm("mov.b64 %0,{%1,%2};" : "=l"(r) : "f"(lo), "f"(hi)); return r;
}
__device__ __forceinline__ void upk(float& lo, float& hi, u64 p){
  asm("mov.b64 {%0,%1},%2;" : "=f"(lo), "=f"(hi) : "l"(p));
}
__device__ __forceinline__ u64 fma2(u64 a, u64 b, u64 c){
  u64 d; asm("fma.rn.f32x2 %0,%1,%2,%3;" : "=l"(d) : "l"(a), "l"(b), "l"(c)); return d;
}
__device__ __forceinline__ u64 add2(u64 a, u64 b){
  u64 d; asm("add.rn.f32x2 %0,%1,%2;" : "=l"(d) : "l"(a), "l"(b)); return d;
}
__device__ __forceinline__ float hsum(u64 p){
  float lo, hi; upk(lo, hi, p); return lo + hi;
}
// f32 -> fp16 bits (low 16, duplicated high for cheap PRMT pairing)
__device__ __forceinline__ unsigned f2h(float v){
  unsigned r;
  asm("{ .reg .b16 t; cvt.rn.f16.f32 t, %1; mov.b32 %0, {t, t}; }" : "=r"(r) : "f"(v));
  return r;
}
// fp16x2 -> fp32 pair as u64
__device__ __forceinline__ u64 h2up(unsigned p){
  float lo, hi;
  asm("{ .reg .b16 l, h; mov.b32 {l, h}, %2; cvt.f32.f16 %0, l; cvt.f32.f16 %1, h; }"
      : "=f"(lo), "=f"(hi) : "r"(p));
  return pk(lo, hi);
}

extern "C" __global__ void __launch_bounds__(NTHREADS, 1)
mcgru_kernel(const float* __restrict__ x,   const float* __restrict__ Wih,
             const float* __restrict__ Whh, const float* __restrict__ bih,
             const float* __restrict__ bhh, float* __restrict__ out)
{
  __shared__ __align__(16) float xs[2][BPC][ROWPAD];

  const int tid  = threadIdx.x;
  const int w    = tid >> 5;
  const int slot = tid >> 3;
  const int j    = tid & 7;
  const int f    = c_slot_f[slot];
  const int bl   = c_slot_b[slot];
  const bool wen = (bool)c_slot_wr[slot];
  const int mdw  = c_warp_mdw[w];
  const int startf = c_start[f];
  const int bg0  = blockIdx.x * BPC;
  const int m0   = j >> 1;                         // own h-pair index (0..3)
  // pair = (lo = h_even, hi = h_odd): even j contributes lo, odd j hi
  const unsigned psel = (j & 1) ? 0x1054u : 0x5410u;
  // source lanes (within 8-lane group) for the 3 non-local pairs
  const int s1 = 2*((m0 + 1) & 3), s2 = 2*((m0 + 2) & 3), s3 = 2*((m0 + 3) & 3);

  // ---- gx weights: (r,z) packed per dim, pre-scaled 0.5 (tanh-form sigmoid)
  u64 wrz_[13]; float wn_[13];
  {
    const float* Wf = Wih + f*24*13;
    #pragma unroll
    for (int d = 0; d < 13; ++d){
      if (d < mdw){
        wrz_[d] = pk(0.5f*Wf[(0 + j)*13 + d], 0.5f*Wf[(8 + j)*13 + d]);
        wn_[d]  = Wf[(16 + j)*13 + d];
      } else { wrz_[d] = pk(0.f, 0.f); wn_[d] = 0.f; }
    }
  }
  // ---- gh weights: dim-PAIRED and ROTATED so pair i matches Hp[i]
  // (Hp[0] = own pair m0, Hp[i] = pair (m0+i)&3). All pre-scaled 0.5.
  u64 urP[4], uzP[4], unP[4];
  {
    const float* Uf = Whh + f*24*8;
    #pragma unroll
    for (int i = 0; i < 4; ++i){
      int m = (m0 + i) & 3;
      urP[i] = pk(0.5f*Uf[(0 + j)*8 + 2*m], 0.5f*Uf[(0 + j)*8 + 2*m+1]);
      uzP[i] = pk(0.5f*Uf[(8 + j)*8 + 2*m], 0.5f*Uf[(8 + j)*8 + 2*m+1]);
      unP[i] = pk(0.5f*Uf[(16 + j)*8 + 2*m], 0.5f*Uf[(16 + j)*8 + 2*m+1]);
    }
  }
  const u64 brz = pk(0.5f*(bih[f*24 + j]     + bhh[f*24 + j]),
                     0.5f*(bih[f*24 + 8 + j] + bhh[f*24 + 8 + j]));
  const float bxn = bih[f*24 + 16 + j];
  const u64 bhnp = pk(0.5f*bhh[f*24 + 16 + j], 0.f);
  const u64 Z64  = 0ULL;

  // ---- x staging: R4-proven contiguous 16B cp.async double buffer ----
  auto stage = [&](int c, int buf){
    #pragma unroll
    for (int blx = 0; blx < BPC; ++blx){
      const float* src = x + ((size_t)(bg0 + blx)*TSTEPS + (size_t)c*CHK)*XDIM;
      uint32_t dst = (uint32_t)__cvta_generic_to_shared(&xs[buf][blx][0]);
      for (int i = tid; i < (CHK*XDIM)/4; i += NTHREADS)
        cp16(dst + (uint32_t)i*16u, src + i*4);
    }
  };

  stage(0, 0); asm volatile("cp.async.commit_group;" ::: "memory");
  stage(1, 1); asm volatile("cp.async.commit_group;" ::: "memory");

  float h = 0.f;
  u64 Hp[4] = {0ULL, 0ULL, 0ULL, 0ULL};            // fp32 h-pairs (h0 = 0)
  float* outp = out + (((size_t)(bg0 + bl)*TSTEPS)*NFEAT + f)*HDIM + j;

  auto run_chunk = [&](auto Dc, const float* xbase, float* outc){
    constexpr int D = decltype(Dc)::value;
    #pragma unroll 4
    for (int tl = 0; tl < CHK; ++tl){
      // gates_x (h-independent; hides previous step's transport latency)
      const float* xp = xbase + tl*XDIM;
      u64 grz = brz; float gn = bxn;
      #pragma unroll
      for (int d = 0; d < D; ++d){
        float xv = xp[d];
        grz = fma2(wrz_[d], pk(xv, xv), grz);
        gn  = fmaf(wn_[d], xv, gn);
      }
      // gh: dim-paired fma2 over carried fp32 h-pairs (no SHFL here)
      u64 rA = fma2(urP[0], Hp[0], Z64);  rA = fma2(urP[1], Hp[1], rA);
      u64 rB = fma2(urP[2], Hp[2], Z64);  rB = fma2(urP[3], Hp[3], rB);
      u64 zA = fma2(uzP[0], Hp[0], Z64);  zA = fma2(uzP[1], Hp[1], zA);
      u64 zB = fma2(uzP[2], Hp[2], Z64);  zB = fma2(uzP[3], Hp[3], zB);
      u64 nA = fma2(unP[0], Hp[0], bhnp); nA = fma2(unP[1], Hp[1], nA);
      u64 nB = fma2(unP[2], Hp[2], Z64);  nB = fma2(unP[3], Hp[3], nB);
      float hr = hsum(add2(rA, rB));
      float hz = hsum(add2(zA, zB));
      float hnh = hsum(add2(nA, nB));              // 0.5*(Un h + bhn)
      float gxr, gxz; upk(gxr, gxz, grz);
      float tr  = tanh_ap(gxr + hr);
      float tz  = tanh_ap(gxz + hz);
      float a   = fmaf(tr, hnh, gn + hnh);         // gn + r*(Un h + bhn)
      float n   = tanh_ap(a);
      float u   = 0.5f*(h - n);
      h = fmaf(tz, u, n + u);                      // (1-z)*n + z*h

      // ---- transport (tail): 4 SHFLs instead of 8, via fp16 pairs
      unsigned hh = f2h(h);                                    // fp16 in both halves
      unsigned nb = __shfl_xor_sync(0xFFFFFFFFu, hh, 1, 8);    // group neighbor
      unsigned pr = __byte_perm(hh, nb, psel);                 // own fp16x2 pair
      unsigned q1 = __shfl_sync(0xFFFFFFFFu, pr, s1, 8);
      unsigned q2 = __shfl_sync(0xFFFFFFFFu, pr, s2, 8);
      unsigned q3 = __shfl_sync(0xFFFFFFFFu, pr, s3, 8);
      Hp[0] = h2up(pr); Hp[1] = h2up(q1); Hp[2] = h2up(q2); Hp[3] = h2up(q3);

      if (wen) outc[(size_t)tl*(NFEAT*HDIM)] = h;
    }
  };

  for (int c = 0; c < NCHK; ++c){
    asm volatile("cp.async.wait_group 1;" ::: "memory");
    __syncthreads();
    const float* xbase = &xs[c & 1][bl][startf];
    float* outc = outp + (size_t)c*CHK*(NFEAT*HDIM);

    if (mdw == 13)      run_chunk(IC<13>{}, xbase, outc);
    else if (mdw == 12) run_chunk(IC<12>{}, xbase, outc);
    else if (mdw == 2)  run_chunk(IC<2>{},  xbase, outc);
    else                run_chunk(IC<1>{},  xbase, outc);

    __syncthreads();
    if (c + 2 < NCHK) stage(c + 2, c & 1);
    asm volatile("cp.async.commit_group;" ::: "memory");
  }
}

extern "C" void kernel_launch(void* const* d_in, const int* in_sizes, int n_in,
                              void* d_out, int out_size)
{
  const float* x   = (const float*)d_in[0];
  const float* Wih = (const float*)d_in[1];
  const float* Whh = (const float*)d_in[2];
  const float* bih = (const float*)d_in[3];
  const float* bhh = (const float*)d_in[4];
  (void)in_sizes; (void)n_in; (void)out_size;
  mcgru_kernel<<<BSZ/BPC, NTHREADS>>>(x, Wih, Whh, bih, bhh, (float*)d_out);
}

// round 16
// speedup vs baseline: 1.1016x; 1.1016x over previous
#include <cuda_runtime.h>
#include <cstdint>
#include <cstddef>

#define NFEAT 17
#define HDIM 8
#define BSZ 256
#define TSTEPS 512
#define XDIM 59
#define CHK 32
#define NCHK (TSTEPS/CHK)
#define BPC 2
#define NTHREADS 288
#define ROWPAD (CHK*XDIM + 16)   // pad so xp[d] overreads stay in-array

typedef unsigned long long u64;

// Chain-to-slot mapping. slot = warp*4 + group. Heavy warps d-homogeneous:
// w1={f3,f3,f2,f2} mdw13 (SMSP1), w2={f4,f4,f1,f1} mdw12 (SMSP2).
__device__ __constant__ int8_t c_slot_f[36] = {
   6, 6, 7, 7,   3, 3, 2, 2,   4, 4, 1, 1,   0, 0, 5, 5,
   8, 8, 9, 9,  10,10,11,11,  12,12,13,13,  14,14,15,15,  16,16,16,16};
__device__ __constant__ int8_t c_slot_b[36] = {
   0, 1, 0, 1,   0, 1, 0, 1,   0, 1, 0, 1,   0, 1, 0, 1,
   0, 1, 0, 1,   0, 1, 0, 1,   0, 1, 0, 1,   0, 1, 0, 1,   0, 1, 0, 1};
__device__ __constant__ int8_t c_slot_wr[36] = {
   1, 1, 1, 1,   1, 1, 1, 1,   1, 1, 1, 1,   1, 1, 1, 1,
   1, 1, 1, 1,   1, 1, 1, 1,   1, 1, 1, 1,   1, 1, 1, 1,   1, 1, 0, 0};
__device__ __constant__ int8_t c_warp_mdw[9] = {1,13,12,2,1,1,1,1,1};
__device__ __constant__ int8_t c_start[17] =
  {0,2,10,22,35,47,48,49,50,51,52,53,54,55,56,57,58};

template<int N> struct IC { static constexpr int value = N; };

__device__ __forceinline__ void cp16(uint32_t s, const float* g){
  asm volatile("cp.async.ca.shared.global [%0], [%1], 16;" :: "r"(s), "l"(g) : "memory");
}
__device__ __forceinline__ float tanh_ap(float x){
  float y; asm("tanh.approx.f32 %0, %1;" : "=f"(y) : "f"(x)); return y;
}
__device__ __forceinline__ u64 pk(float lo, float hi){
  u64 r; asm("mov.b64 %0,{%1,%2};" : "=l"(r) : "f"(lo), "f"(hi)); return r;
}
__device__ __forceinline__ void upk(float& lo, float& hi, u64 p){
  asm("mov.b64 {%0,%1},%2;" : "=f"(lo), "=f"(hi) : "l"(p));
}
__device__ __forceinline__ u64 fma2(u64 a, u64 b, u64 c){
  u64 d; asm("fma.rn.f32x2 %0,%1,%2,%3;" : "=l"(d) : "l"(a), "l"(b), "l"(c)); return d;
}
__device__ __forceinline__ u64 add2(u64 a, u64 b){
  u64 d; asm("add.rn.f32x2 %0,%1,%2;" : "=l"(d) : "l"(a), "l"(b)); return d;
}
__device__ __forceinline__ float hsum(u64 p){
  float lo, hi; upk(lo, hi, p); return lo + hi;
}
__device__ __forceinline__ u64 asu(double d){ return __double_as_longlong(d); }

extern "C" __global__ void __launch_bounds__(NTHREADS, 1)
mcgru_kernel(const float* __restrict__ x,   const float* __restrict__ Wih,
             const float* __restrict__ Whh, const float* __restrict__ bih,
             const float* __restrict__ bhh, float* __restrict__ out)
{
  __shared__ __align__(16) float xs[2][BPC][ROWPAD];   // 30.5 KB, R4 layout
  __shared__ __align__(16) float hsm[36][HDIM];        // h exchange (1.2 KB)

  const int tid  = threadIdx.x;
  const int w    = tid >> 5;
  const int slot = tid >> 3;
  const int j    = tid & 7;
  const int f    = c_slot_f[slot];
  const int bl   = c_slot_b[slot];
  const bool wen = (bool)c_slot_wr[slot];
  const int mdw  = c_warp_mdw[w];
  const int startf = c_start[f];
  const int bg0  = blockIdx.x * BPC;

  // ---- gx weights: (r,z) gate-packed per dim, pre-scaled 0.5
  // (sigmoid(x) = 0.5 + 0.5*tanh(x/2)); hh n-path pre-scaled 0.5.
  u64 wrz_[13]; float wn_[13];
  {
    const float* Wf = Wih + f*24*13;
    #pragma unroll
    for (int d = 0; d < 13; ++d){
      if (d < mdw){
        wrz_[d] = pk(0.5f*Wf[(0 + j)*13 + d], 0.5f*Wf[(8 + j)*13 + d]);
        wn_[d]  = Wf[(16 + j)*13 + d];
      } else { wrz_[d] = pk(0.f, 0.f); wn_[d] = 0.f; }
    }
  }
  // ---- gh weights: k-PAIRED u64 (R8-proven form), pre-scaled 0.5
  u64 urp[4], uzp[4], unp[4];
  {
    const float* Uf = Whh + f*24*8;
    #pragma unroll
    for (int p = 0; p < 4; ++p){
      urp[p] = pk(0.5f*Uf[(0 + j)*8 + 2*p], 0.5f*Uf[(0 + j)*8 + 2*p+1]);
      uzp[p] = pk(0.5f*Uf[(8 + j)*8 + 2*p], 0.5f*Uf[(8 + j)*8 + 2*p+1]);
      unp[p] = pk(0.5f*Uf[(16 + j)*8 + 2*p], 0.5f*Uf[(16 + j)*8 + 2*p+1]);
    }
  }
  const u64 brz = pk(0.5f*(bih[f*24 + j]     + bhh[f*24 + j]),
                     0.5f*(bih[f*24 + 8 + j] + bhh[f*24 + 8 + j]));
  const float bxn = bih[f*24 + 16 + j];
  const u64 bhnp = pk(0.5f*bhh[f*24 + 16 + j], 0.f);
  const u64 Z64  = 0ULL;

  hsm[slot][j] = 0.f;                  // h0 = 0 (exactly 288 threads = 288 cells)

  // ---- staging: R4-proven contiguous 16B cp.async double buffer ----
  auto stage = [&](int c, int buf){
    #pragma unroll
    for (int blx = 0; blx < BPC; ++blx){
      const float* src = x + ((size_t)(bg0 + blx)*TSTEPS + (size_t)c*CHK)*XDIM;
      uint32_t dst = (uint32_t)__cvta_generic_to_shared(&xs[buf][blx][0]);
      for (int i = tid; i < (CHK*XDIM)/4; i += NTHREADS)
        cp16(dst + (uint32_t)i*16u, src + i*4);
    }
  };

  stage(0, 0); asm volatile("cp.async.commit_group;" ::: "memory");
  stage(1, 1); asm volatile("cp.async.commit_group;" ::: "memory");

  float h = 0.f;
  float* outp = out + (((size_t)(bg0 + bl)*TSTEPS)*NFEAT + f)*HDIM + j;
  const double2* hq = (const double2*)&hsm[slot][0];

  auto run_chunk = [&](auto Dc, const float* xbase, float* outc){
    constexpr int D = decltype(Dc)::value;
    #pragma unroll 4
    for (int tl = 0; tl < CHK; ++tl){
      // gates_x (h-independent; fills STS->LDS distance of the exchange)
      const float* xp = xbase + tl*XDIM;
      u64 grz = brz; float gn = bxn;
      #pragma unroll
      for (int d = 0; d < D; ++d){
        float xv = xp[d];
        grz = fma2(wrz_[d], pk(xv, xv), grz);
        gn  = fmaf(wn_[d], xv, gn);
      }
      // ---- h exchange: 2x LDS.128 instead of 8 SHFLs (MIO: 8 ops -> 2)
      __syncwarp();
      double2 a0 = hq[0], a1 = hq[1];
      u64 H0 = asu(a0.x), H1 = asu(a0.y), H2 = asu(a1.x), H3 = asu(a1.y);
      // gh: k-paired fma2, zero packing movs
      u64 rA = fma2(urp[0], H0, Z64);  rA = fma2(urp[1], H1, rA);
      u64 rB = fma2(urp[2], H2, Z64);  rB = fma2(urp[3], H3, rB);
      u64 zA = fma2(uzp[0], H0, Z64);  zA = fma2(uzp[1], H1, zA);
      u64 zB = fma2(uzp[2], H2, Z64);  zB = fma2(uzp[3], H3, zB);
      u64 nA = fma2(unp[0], H0, bhnp); nA = fma2(unp[1], H1, nA);
      u64 nB = fma2(unp[2], H2, Z64);  nB = fma2(unp[3], H3, nB);
      float hr  = hsum(add2(rA, rB));
      float hz  = hsum(add2(zA, zB));
      float hnh = hsum(add2(nA, nB));              // 0.5*(Un h + bhn)
      float gxr, gxz; upk(gxr, gxz, grz);
      float tr  = tanh_ap(gxr + hr);
      float tz  = tanh_ap(gxz + hz);
      float a   = fmaf(tr, hnh, gn + hnh);         // gn + r*(Un h + bhn)
      float n   = tanh_ap(a);
      float u   = 0.5f*(h - n);
      h = fmaf(tz, u, n + u);                      // (1-z)*n + z*h
      hsm[slot][j] = h;                            // publish (1 STS)
      if (wen) outc[(size_t)tl*(NFEAT*HDIM)] = h;
    }
  };

  for (int c = 0; c < NCHK; ++c){
    asm volatile("cp.async.wait_group 1;" ::: "memory");
    __syncthreads();
    const float* xbase = &xs[c & 1][bl][startf];
    float* outc = outp + (size_t)c*CHK*(NFEAT*HDIM);

    if (mdw == 13)      run_chunk(IC<13>{}, xbase, outc);
    else if (mdw == 12) run_chunk(IC<12>{}, xbase, outc);
    else if (mdw == 2)  run_chunk(IC<2>{},  xbase, outc);
    else                run_chunk(IC<1>{},  xbase, outc);

    __syncthreads();
    if (c + 2 < NCHK) stage(c + 2, c & 1);
    asm volatile("cp.async.commit_group;" ::: "memory");
  }
}

extern "C" void kernel_launch(void* const* d_in, const int* in_sizes, int n_in,
                              void* d_out, int out_size)
{
  const float* x   = (const float*)d_in[0];
  const float* Wih = (const float*)d_in[1];
  const float* Whh = (const float*)d_in[2];
  const float* bih = (const float*)d_in[3];
  const float* bhh = (const float*)d_in[4];
  (void)in_sizes; (void)n_in; (void)out_size;
  mcgru_kernel<<<BSZ/BPC, NTHREADS>>>(x, Wih, Whh, bih, bhh, (float*)d_out);
}

// round 17
// speedup vs baseline: 1.1443x; 1.0388x over previous
#include <cuda_runtime.h>
#include <cstdint>
#include <cstddef>

#define NFEAT 17
#define HDIM 8
#define BSZ 256
#define TSTEPS 512
#define XDIM 59
#define CHK 32
#define NCHK (TSTEPS/CHK)
#define BPC 2
#define NTHREADS 288
#define ROWPAD (CHK*XDIM + 16)   // pad so xp[d] overreads stay in-array

typedef unsigned long long u64;

// Chain-to-slot mapping. slot = warp*4 + group. Heavy warps d-homogeneous:
// w1={f3,f3,f2,f2} mdw13 (SMSP1), w2={f4,f4,f1,f1} mdw12 (SMSP2).
__device__ __constant__ int8_t c_slot_f[36] = {
   6, 6, 7, 7,   3, 3, 2, 2,   4, 4, 1, 1,   0, 0, 5, 5,
   8, 8, 9, 9,  10,10,11,11,  12,12,13,13,  14,14,15,15,  16,16,16,16};
__device__ __constant__ int8_t c_slot_b[36] = {
   0, 1, 0, 1,   0, 1, 0, 1,   0, 1, 0, 1,   0, 1, 0, 1,
   0, 1, 0, 1,   0, 1, 0, 1,   0, 1, 0, 1,   0, 1, 0, 1,   0, 1, 0, 1};
__device__ __constant__ int8_t c_slot_wr[36] = {
   1, 1, 1, 1,   1, 1, 1, 1,   1, 1, 1, 1,   1, 1, 1, 1,
   1, 1, 1, 1,   1, 1, 1, 1,   1, 1, 1, 1,   1, 1, 1, 1,   1, 1, 0, 0};
__device__ __constant__ int8_t c_warp_mdw[9] = {1,13,12,2,1,1,1,1,1};
__device__ __constant__ int8_t c_start[17] =
  {0,2,10,22,35,47,48,49,50,51,52,53,54,55,56,57,58};

template<int N> struct IC { static constexpr int value = N; };

__device__ __forceinline__ void cp16(uint32_t s, const float* g){
  asm volatile("cp.async.ca.shared.global [%0], [%1], 16;" :: "r"(s), "l"(g) : "memory");
}
__device__ __forceinline__ float tanh_ap(float x){
  float y; asm("tanh.approx.f32 %0, %1;" : "=f"(y) : "f"(x)); return y;
}
__device__ __forceinline__ u64 pk(float lo, float hi){
  u64 r; asm("mov.b64 %0,{%1,%2};" : "=l"(r) : "f"(lo), "f"(hi)); return r;
}
__device__ __forceinline__ void upk(float& lo, float& hi, u64 p){
  asm("mov.b64 {%0,%1},%2;" : "=f"(lo), "=f"(hi) : "l"(p));
}
__device__ __forceinline__ u64 fma2(u64 a, u64 b, u64 c){
  u64 d; asm("fma.rn.f32x2 %0,%1,%2,%3;" : "=l"(d) : "l"(a), "l"(b), "l"(c)); return d;
}
__device__ __forceinline__ u64 add2(u64 a, u64 b){
  u64 d; asm("add.rn.f32x2 %0,%1,%2;" : "=l"(d) : "l"(a), "l"(b)); return d;
}

extern "C" __global__ void __launch_bounds__(NTHREADS, 1)
mcgru_kernel(const float* __restrict__ x,   const float* __restrict__ Wih,
             const float* __restrict__ Whh, const float* __restrict__ bih,
             const float* __restrict__ bhh, float* __restrict__ out)
{
  __shared__ __align__(16) float xs[2][BPC][ROWPAD];

  const int tid  = threadIdx.x;
  const int w    = tid >> 5;
  const int slot = tid >> 3;
  const int j    = tid & 7;
  const int f    = c_slot_f[slot];
  const int bl   = c_slot_b[slot];
  const bool wen = (bool)c_slot_wr[slot];
  const int mdw  = c_warp_mdw[w];
  const int startf = c_start[f];
  const int bg0  = blockIdx.x * BPC;

  // ---- weights in registers; (r,z) pairs packed as f32x2, pre-scaled by 0.5
  // (sigmoid(x) = 0.5 + 0.5*tanh(x/2)); hh n-path pre-scaled by 0.5.
  u64 wrz_[13]; float wn_[13];
  {
    const float* Wf = Wih + f*24*13;
    #pragma unroll
    for (int d = 0; d < 13; ++d){
      if (d < mdw){
        wrz_[d] = pk(0.5f*Wf[(0 + j)*13 + d], 0.5f*Wf[(8 + j)*13 + d]);
        wn_[d]  = Wf[(16 + j)*13 + d];
      } else { wrz_[d] = pk(0.f, 0.f); wn_[d] = 0.f; }
    }
  }
  u64 urz_[8]; float un_[8];
  {
    const float* Uf = Whh + f*24*8;
    #pragma unroll
    for (int k = 0; k < 8; ++k){
      urz_[k] = pk(0.5f*Uf[(0 + j)*8 + k], 0.5f*Uf[(8 + j)*8 + k]);
      un_[k]  = 0.5f*Uf[(16 + j)*8 + k];
    }
  }
  const u64 brz = pk(0.5f*(bih[f*24 + j]     + bhh[f*24 + j]),
                     0.5f*(bih[f*24 + 8 + j] + bhh[f*24 + 8 + j]));
  const float bxn = bih[f*24 + 16 + j];
  const float bhn = 0.5f*bhh[f*24 + 16 + j];

  // ---- x staging: cp.async double buffer, CHK timesteps per chunk ----
  auto stage = [&](int c, int buf){
    #pragma unroll
    for (int blx = 0; blx < BPC; ++blx){
      const float* src = x + ((size_t)(bg0 + blx)*TSTEPS + (size_t)c*CHK)*XDIM;
      uint32_t dst = (uint32_t)__cvta_generic_to_shared(&xs[buf][blx][0]);
      for (int i = tid; i < (CHK*XDIM)/4; i += NTHREADS)
        cp16(dst + (uint32_t)i*16u, src + i*4);
    }
  };

  stage(0, 0); asm volatile("cp.async.commit_group;" ::: "memory");
  stage(1, 1); asm volatile("cp.async.commit_group;" ::: "memory");

  float h = 0.f;
  // vector store base: lane j stores the 16B block starting at (j & 4)
  float* outv = out + (((size_t)(bg0 + bl)*TSTEPS)*NFEAT + f)*HDIM + (j & 4);
  const bool wv = wen && ((j & 3) == 0);   // lanes 0 and 4 of each group write

  auto run_chunk = [&](auto Dc, const float* xbase, float* outc){
    constexpr int D = decltype(Dc)::value;
    // hk carried across iterations: refreshed at the TAIL of each step so the
    // next step's h-independent gx block hides the 26-cyc SHFL latency, and
    // the refreshed hk doubles as the pack source for vectorized stores.
    float hk[8];
    #pragma unroll
    for (int k = 0; k < 8; ++k) hk[k] = __shfl_sync(0xFFFFFFFFu, h, k, 8);

    #pragma unroll 4
    for (int tl = 0; tl < CHK; ++tl){
      // gates_x (h-independent; executes under the previous step's SHFLs)
      const float* xp = xbase + tl*XDIM;
      u64 grz = brz; float gn = bxn;
      #pragma unroll
      for (int d = 0; d < D; ++d){
        float xv = xp[d];
        grz = fma2(wrz_[d], pk(xv, xv), grz);
        gn  = fmaf(wn_[d], xv, gn);
      }
      // gh: uses the pre-broadcast hk (no SHFL at the head of the chain)
      u64 hrz0 = pk(0.f, 0.f), hrz1 = pk(0.f, 0.f);
      float hnA = bhn, hnB = 0.f;
      #pragma unroll
      for (int k = 0; k < 4; ++k){
        hrz0 = fma2(urz_[k],   pk(hk[k],   hk[k]),   hrz0);
        hrz1 = fma2(urz_[k+4], pk(hk[k+4], hk[k+4]), hrz1);
        hnA  = fmaf(un_[k],   hk[k],   hnA);
        hnB  = fmaf(un_[k+4], hk[k+4], hnB);
      }
      u64 arz = add2(grz, add2(hrz0, hrz1));
      float ar, az; upk(ar, az, arz);
      float tr  = tanh_ap(ar);
      float tz  = tanh_ap(az);
      float hnh = hnA + hnB;                       // 0.5 * (Un h + bhn)
      float a   = fmaf(tr, hnh, gn + hnh);         // gn + r*(Un h + bhn)
      float n   = tanh_ap(a);
      float u   = 0.5f*(h - n);
      h = fmaf(tz, u, n + u);                      // (1-z)*n + z*h
      // refresh the broadcast immediately (tail of the serial chain)
      #pragma unroll
      for (int k = 0; k < 8; ++k) hk[k] = __shfl_sync(0xFFFFFFFFu, h, k, 8);
      // vectorized store: 2 STG.128 per group instead of 8 STG.32
      if (wv){
        float4 v = (j & 4) ? make_float4(hk[4], hk[5], hk[6], hk[7])
                           : make_float4(hk[0], hk[1], hk[2], hk[3]);
        *(float4*)(outc + (size_t)tl*(NFEAT*HDIM)) = v;
      }
    }
  };

  for (int c = 0; c < NCHK; ++c){
    asm volatile("cp.async.wait_group 1;" ::: "memory");
    __syncthreads();
    const float* xbase = &xs[c & 1][bl][startf];
    float* outc = outv + (size_t)c*CHK*(NFEAT*HDIM);

    if (mdw == 13)      run_chunk(IC<13>{}, xbase, outc);
    else if (mdw == 12) run_chunk(IC<12>{}, xbase, outc);
    else if (mdw == 2)  run_chunk(IC<2>{},  xbase, outc);
    else                run_chunk(IC<1>{},  xbase, outc);

    __syncthreads();
    if (c + 2 < NCHK) stage(c + 2, c & 1);
    asm volatile("cp.async.commit_group;" ::: "memory");
  }
}

extern "C" void kernel_launch(void* const* d_in, const int* in_sizes, int n_in,
                              void* d_out, int out_size)
{
  const float* x   = (const float*)d_in[0];
  const float* Wih = (const float*)d_in[1];
  const float* Whh = (const float*)d_in[2];
  const float* bih = (const float*)d_in[3];
  const float* bhh = (const float*)d_in[4];
  (void)in_sizes; (void)n_in; (void)out_size;
  mcgru_kernel<<<BSZ/BPC, NTHREADS>>>(x, Wih, Whh, bih, bhh, (float*)d_out);
}